// round 11
// baseline (speedup 1.0000x reference)
#include <cuda_runtime.h>
#include <cuda_fp16.h>
#include <cstdint>

#define D 64
#define MAXNTOT 340008
#define MAXNNZALL 4000008
#define SCAN_B 256
#define MAXBLKS ((150016 + SCAN_B - 1) / SCAN_B)
#define DBINS 64

// ---- scratch (__device__ globals; no allocation allowed) ----
__device__ __align__(16) __half g_f0[(size_t)MAXNTOT * D];   // ~43.5 MB
__device__ __align__(16) __half g_f1[(size_t)MAXNTOT * D];   // ~43.5 MB
__device__ __align__(16) float2 g_edges[MAXNNZALL];          // {global col bits, val}
__device__ int g_counts[MAXNTOT];
__device__ int g_offs[MAXNTOT + 1];
__device__ int g_cursor[MAXNTOT];
__device__ int g_perm[MAXNTOT];          // rows sorted by degree bin
__device__ int g_dhist[DBINS];           // degree histogram / cursors
__device__ unsigned long long g_desc[3][MAXBLKS];
__device__ unsigned int g_ticket[3];

// ---- init: f0(fp16) = concat of all three propagation inputs ----
__global__ void init_kernel(const float* __restrict__ Uf, const float* __restrict__ If,
                            const float* __restrict__ Bf,
                            int U, int NB, int R1, int R2, int ntot,
                            __half* __restrict__ f0) {
    int idx = blockIdx.x * blockDim.x + threadIdx.x;
    if (idx >= ntot * (D / 4)) return;
    int row = idx >> 4;
    int c = (idx & 15) * 4;
    const float* src;
    if (row < R1) {
        src = (row < U) ? (Uf + (size_t)row * D) : (If + (size_t)(row - U) * D);
    } else if (row < R2) {
        int l = row - R1;
        src = (l < NB) ? (Bf + (size_t)l * D) : (If + (size_t)(l - NB) * D);
    } else {
        int l = row - R2;
        src = (l < U) ? (Uf + (size_t)l * D) : (Bf + (size_t)(l - U) * D);
    }
    float4 v = *(const float4*)(src + c);
    __half2 h0 = __floats2half2_rn(v.x, v.y);
    __half2 h1 = __floats2half2_rn(v.z, v.w);
    uint2 packed;
    packed.x = *(const unsigned int*)&h0;
    packed.y = *(const unsigned int*)&h1;
    *(uint2*)(f0 + (size_t)row * D + c) = packed;
}

// ---- per-graph histogram (4 edges/thread) ----
__global__ void hist_kernel(const int* __restrict__ rows, int nnz, int* __restrict__ counts) {
    int base = (blockIdx.x * blockDim.x + threadIdx.x) * 4;
    if (base + 4 <= nnz) {
        int4 r = *(const int4*)(rows + base);
        atomicAdd(&counts[r.x], 1); atomicAdd(&counts[r.y], 1);
        atomicAdd(&counts[r.z], 1); atomicAdd(&counts[r.w], 1);
    } else {
        for (int k = base; k < nnz; k++) atomicAdd(&counts[rows[k]], 1);
    }
}

// ---- degree-bin histogram over all rows ----
__global__ void dhist_kernel(const int* __restrict__ counts, int ntot, int* __restrict__ dh) {
    int base = (blockIdx.x * blockDim.x + threadIdx.x) * 4;
    if (base + 4 <= ntot) {
        int4 c = *(const int4*)(counts + base);
        atomicAdd(&dh[min(c.x, DBINS - 1)], 1);
        atomicAdd(&dh[min(c.y, DBINS - 1)], 1);
        atomicAdd(&dh[min(c.z, DBINS - 1)], 1);
        atomicAdd(&dh[min(c.w, DBINS - 1)], 1);
    } else {
        for (int k = base; k < ntot; k++) atomicAdd(&dh[min(counts[k], DBINS - 1)], 1);
    }
}

// ---- tiny exclusive scan of the 64 bins -> cursors ----
__global__ void dscan_kernel(int* __restrict__ dh) {
    __shared__ int sm[DBINS];
    int t = threadIdx.x;
    int v = dh[t];
    sm[t] = v;
    __syncthreads();
    #pragma unroll
    for (int o = 1; o < DBINS; o <<= 1) {
        int u = (t >= o) ? sm[t - o] : 0;
        __syncthreads();
        sm[t] += u;
        __syncthreads();
    }
    dh[t] = sm[t] - v;   // exclusive
}

// ---- scatter rows into perm grouped by degree bin ----
__global__ void dscatter_kernel(const int* __restrict__ counts, int ntot,
                                int* __restrict__ dh, int* __restrict__ perm) {
    int base = (blockIdx.x * blockDim.x + threadIdx.x) * 4;
    if (base + 4 <= ntot) {
        int4 c = *(const int4*)(counts + base);
        int p0 = atomicAdd(&dh[min(c.x, DBINS - 1)], 1);
        int p1 = atomicAdd(&dh[min(c.y, DBINS - 1)], 1);
        int p2 = atomicAdd(&dh[min(c.z, DBINS - 1)], 1);
        int p3 = atomicAdd(&dh[min(c.w, DBINS - 1)], 1);
        perm[p0] = base;
        perm[p1] = base + 1;
        perm[p2] = base + 2;
        perm[p3] = base + 3;
    } else {
        for (int k = base; k < ntot; k++) {
            int pos = atomicAdd(&dh[min(counts[k], DBINS - 1)], 1);
            perm[pos] = k;
        }
    }
}

// ---- per-graph decoupled-lookback scan; writes GLOBAL offsets (base = edge base) ----
__global__ void scan_kernel(const int* __restrict__ counts, int n, int base,
                            int* __restrict__ offs, int* __restrict__ cursor,
                            unsigned long long* __restrict__ desc,
                            unsigned int* __restrict__ ticket) {
    __shared__ int s_warp[8];
    __shared__ int s_bid;
    __shared__ int s_excl;
    int lane = threadIdx.x & 31;
    int wid = threadIdx.x >> 5;
    if (threadIdx.x == 0) s_bid = (int)atomicAdd(ticket, 1u);
    __syncthreads();
    int bid = s_bid;
    int i = bid * SCAN_B + threadIdx.x;
    int v = (i < n) ? counts[i] : 0;
    int x = v;
    #pragma unroll
    for (int o = 1; o < 32; o <<= 1) {
        int t = __shfl_up_sync(0xffffffffu, x, o);
        if (lane >= o) x += t;
    }
    if (lane == 31) s_warp[wid] = x;
    __syncthreads();
    if (wid == 0 && lane < 8) {
        int w = s_warp[lane];
        #pragma unroll
        for (int o = 1; o < 8; o <<= 1) {
            int t = __shfl_up_sync(0xffu, w, o);
            if (lane >= o) w += t;
        }
        s_warp[lane] = w;
    }
    __syncthreads();
    int incl = x + (wid ? s_warp[wid - 1] : 0);
    int total = s_warp[7];
    if (threadIdx.x == 0) {
        if (bid == 0) {
            atomicExch(&desc[0], (2ULL << 62) | (unsigned long long)(unsigned)total);
            s_excl = 0;
        } else {
            atomicExch(&desc[bid], (1ULL << 62) | (unsigned long long)(unsigned)total);
            int excl = 0;
            int j = bid - 1;
            while (true) {
                unsigned long long d;
                do { d = atomicAdd(&desc[j], 0ULL); } while ((d >> 62) == 0ULL);
                excl += (int)(unsigned)d;
                if ((d >> 62) == 2ULL) break;
                j--;
            }
            s_excl = excl;
            atomicExch(&desc[bid], (2ULL << 62) | (unsigned long long)(unsigned)(excl + total));
        }
    }
    __syncthreads();
    int excl = s_excl;
    if (i < n) {
        int inc = incl + excl + base;
        offs[i + 1] = inc;
        cursor[i] = inc - v;
        if (i == 0) offs[0] = base;
    }
}

// ---- per-graph bucket: edges -> (GLOBAL col = local + cbase, val) ----
__global__ void bucket_kernel(const int* __restrict__ rows, const int* __restrict__ cols,
                              const float* __restrict__ vals, int nnz, int cbase,
                              int* __restrict__ cursor, float2* __restrict__ edges) {
    int base = (blockIdx.x * blockDim.x + threadIdx.x) * 4;
    if (base + 4 <= nnz) {
        int4 r = *(const int4*)(rows + base);
        int4 c = *(const int4*)(cols + base);
        float4 v = *(const float4*)(vals + base);
        int p0 = atomicAdd(&cursor[r.x], 1);
        int p1 = atomicAdd(&cursor[r.y], 1);
        int p2 = atomicAdd(&cursor[r.z], 1);
        int p3 = atomicAdd(&cursor[r.w], 1);
        edges[p0] = make_float2(__int_as_float(c.x + cbase), v.x);
        edges[p1] = make_float2(__int_as_float(c.y + cbase), v.y);
        edges[p2] = make_float2(__int_as_float(c.z + cbase), v.z);
        edges[p3] = make_float2(__int_as_float(c.w + cbase), v.w);
    } else {
        for (int k = base; k < nnz; k++) {
            int pos = atomicAdd(&cursor[rows[k]], 1);
            edges[pos] = make_float2(__int_as_float(cols[k] + cbase), vals[k]);
        }
    }
}

// map global row -> output row pointer (fixed packing of the 6 tables)
__device__ __forceinline__ float* out_ptr(float* out, int row, int U, int NI, int NB,
                                          int R1, int R2) {
    size_t off;
    if (row < R1) {
        off = (row < U) ? (size_t)row : (size_t)(2 * U + 2 * NB) + (row - U);
    } else if (row < R2) {
        int l = row - R1;
        off = (l < NB) ? (size_t)(2 * U) + l : (size_t)(2 * U + 2 * NB + NI) + (l - NB);
    } else {
        int l = row - R2;
        off = (l < U) ? (size_t)U + l : (size_t)(2 * U + NB) + (l - U);
    }
    return out + off * D;
}

#define EPAD make_float2(__int_as_float(0), 0.0f)

__device__ __forceinline__ void fma8(float* acc, float w, uint4 r) {
    float2 p0 = __half22float2(*(__half2*)&r.x);
    float2 p1 = __half22float2(*(__half2*)&r.y);
    float2 p2 = __half22float2(*(__half2*)&r.z);
    float2 p3 = __half22float2(*(__half2*)&r.w);
    acc[0] += w * p0.x; acc[1] += w * p0.y;
    acc[2] += w * p1.x; acc[3] += w * p1.y;
    acc[4] += w * p2.x; acc[5] += w * p2.y;
    acc[6] += w * p3.x; acc[7] += w * p3.y;
}

// ---- fused gather-SpMM: one row per 8-lane quarter, rows taken from the
// degree-sorted perm so all 4 quarters of a warp have near-equal degree.
template <bool FIRST>
__global__ void __launch_bounds__(256)
spmm_kernel(const float2* __restrict__ edges, const int* __restrict__ offs,
            const int* __restrict__ perm,
            const __half* __restrict__ fin, __half* __restrict__ fnext,
            int ntot, int U, int NI, int NB, int R1, int R2,
            float* __restrict__ out) {
    int warp = blockIdx.x * (blockDim.x >> 5) + (threadIdx.x >> 5);
    int lane = threadIdx.x & 31;
    int quarter = lane >> 3;
    int sub = lane & 7;
    int idx = warp * 4 + quarter;
    if (idx >= ntot) return;
    int row = __ldg(perm + idx);
    unsigned qmask = 0xffu << (quarter * 8);

    int lo = __ldg(offs + row), hi = __ldg(offs + row + 1);

    float acc[8] = {0.f, 0.f, 0.f, 0.f, 0.f, 0.f, 0.f, 0.f};
    int i = lo;
    if (i < hi) {
        float2 c0 = __ldg(edges + i);
        float2 c1 = (i + 1 < hi) ? __ldg(edges + i + 1) : EPAD;
        float2 c2 = (i + 2 < hi) ? __ldg(edges + i + 2) : EPAD;
        float2 c3 = (i + 3 < hi) ? __ldg(edges + i + 3) : EPAD;
        while (true) {
            uint4 r0 = *((const uint4*)(fin + (size_t)__float_as_int(c0.x) * D) + sub);
            uint4 r1 = *((const uint4*)(fin + (size_t)__float_as_int(c1.x) * D) + sub);
            uint4 r2 = *((const uint4*)(fin + (size_t)__float_as_int(c2.x) * D) + sub);
            uint4 r3 = *((const uint4*)(fin + (size_t)__float_as_int(c3.x) * D) + sub);
            i += 4;
            bool more = (i < hi);
            float2 n0, n1, n2, n3;
            if (more) {
                n0 = __ldg(edges + i);
                n1 = (i + 1 < hi) ? __ldg(edges + i + 1) : EPAD;
                n2 = (i + 2 < hi) ? __ldg(edges + i + 2) : EPAD;
                n3 = (i + 3 < hi) ? __ldg(edges + i + 3) : EPAD;
            }
            fma8(acc, c0.y, r0);
            fma8(acc, c1.y, r1);
            fma8(acc, c2.y, r2);
            fma8(acc, c3.y, r3);
            if (!more) break;
            c0 = n0; c1 = n1; c2 = n2; c3 = n3;
        }
    }
    float ss = acc[0] * acc[0] + acc[1] * acc[1] + acc[2] * acc[2] + acc[3] * acc[3]
             + acc[4] * acc[4] + acc[5] * acc[5] + acc[6] * acc[6] + acc[7] * acc[7];
    #pragma unroll
    for (int o = 4; o; o >>= 1) ss += __shfl_xor_sync(qmask, ss, o);
    const float k = 1.0f / 3.0f;
    float scale = k / fmaxf(sqrtf(ss), 1e-12f);

    float* dst = out_ptr(out, row, U, NI, NB, R1, R2);
    if (FIRST) {
        __half2 h0 = __floats2half2_rn(acc[0], acc[1]);
        __half2 h1 = __floats2half2_rn(acc[2], acc[3]);
        __half2 h2 = __floats2half2_rn(acc[4], acc[5]);
        __half2 h3 = __floats2half2_rn(acc[6], acc[7]);
        uint4 packed;
        packed.x = *(const unsigned int*)&h0;
        packed.y = *(const unsigned int*)&h1;
        packed.z = *(const unsigned int*)&h2;
        packed.w = *(const unsigned int*)&h3;
        *((uint4*)(fnext + (size_t)row * D) + sub) = packed;
        uint4 r = *((const uint4*)(fin + (size_t)row * D) + sub);
        float2 p0 = __half22float2(*(__half2*)&r.x);
        float2 p1 = __half22float2(*(__half2*)&r.y);
        float2 p2 = __half22float2(*(__half2*)&r.z);
        float2 p3 = __half22float2(*(__half2*)&r.w);
        float4* d = (float4*)dst + sub * 2;
        d[0] = make_float4(p0.x * k + acc[0] * scale, p0.y * k + acc[1] * scale,
                           p1.x * k + acc[2] * scale, p1.y * k + acc[3] * scale);
        d[1] = make_float4(p2.x * k + acc[4] * scale, p2.y * k + acc[5] * scale,
                           p3.x * k + acc[6] * scale, p3.y * k + acc[7] * scale);
    } else {
        float4* d = (float4*)dst + sub * 2;
        float4 o0 = d[0], o1 = d[1];
        o0.x += acc[0] * scale; o0.y += acc[1] * scale;
        o0.z += acc[2] * scale; o0.w += acc[3] * scale;
        o1.x += acc[4] * scale; o1.y += acc[5] * scale;
        o1.z += acc[6] * scale; o1.w += acc[7] * scale;
        d[0] = o0; d[1] = o1;
    }
}

// ---- persistent streams/events ----
static cudaStream_t s_strm[3];
static cudaEvent_t s_root, s_hist[3], s_done[3];
static bool s_ready = false;

extern "C" void kernel_launch(void* const* d_in, const int* in_sizes, int n_in,
                              void* d_out, int out_size) {
    const float* users_feature   = (const float*)d_in[0];
    const float* items_feature   = (const float*)d_in[1];
    const float* bundles_feature = (const float*)d_in[2];
    const float* vals_[3] = {(const float*)d_in[3], (const float*)d_in[4], (const float*)d_in[5]};
    const int* rows_[3] = {(const int*)d_in[6], (const int*)d_in[8], (const int*)d_in[10]};
    const int* cols_[3] = {(const int*)d_in[7], (const int*)d_in[9], (const int*)d_in[11]};

    int U  = in_sizes[0] / D;
    int NI = in_sizes[1] / D;
    int NB = in_sizes[2] / D;
    int nnz_[3] = {in_sizes[3], in_sizes[4], in_sizes[5]};   // UI, BI, UB

    int R1 = U + NI;
    int R2 = R1 + NB + NI;
    int ntot = R2 + U + NB;

    if (!s_ready) {
        for (int g = 0; g < 3; g++) {
            cudaStreamCreateWithFlags(&s_strm[g], cudaStreamNonBlocking);
            cudaEventCreateWithFlags(&s_hist[g], cudaEventDisableTiming);
            cudaEventCreateWithFlags(&s_done[g], cudaEventDisableTiming);
        }
        cudaEventCreateWithFlags(&s_root, cudaEventDisableTiming);
        s_ready = true;
    }

    float* out = (float*)d_out;
    __half *f0, *f1;
    float2* edges;
    int *counts, *offs, *cursor, *perm, *dhist;
    unsigned long long* desc;
    unsigned int* ticket;
    cudaGetSymbolAddress((void**)&f0, g_f0);
    cudaGetSymbolAddress((void**)&f1, g_f1);
    cudaGetSymbolAddress((void**)&edges, g_edges);
    cudaGetSymbolAddress((void**)&counts, g_counts);
    cudaGetSymbolAddress((void**)&offs, g_offs);
    cudaGetSymbolAddress((void**)&cursor, g_cursor);
    cudaGetSymbolAddress((void**)&perm, g_perm);
    cudaGetSymbolAddress((void**)&dhist, g_dhist);
    cudaGetSymbolAddress((void**)&desc, g_desc);
    cudaGetSymbolAddress((void**)&ticket, g_ticket);

    struct G { int rbase, n, ebase; };
    G gs[3] = {
        {0,  U + NI,  0},
        {R1, NB + NI, nnz_[0]},
        {R2, U + NB,  nnz_[0] + nnz_[1]},
    };

    // fork: per-graph CSR builds on 3 side streams; init + degree-sort on main
    cudaEventRecord(s_root, 0);
    for (int g = 0; g < 3; g++) {
        cudaStream_t st = s_strm[g];
        const G& G_ = gs[g];
        int n = G_.n;
        int nb = (n + SCAN_B - 1) / SCAN_B;
        int* cnt = counts + G_.rbase;
        int* off = offs + G_.rbase;
        int* cur = cursor + G_.rbase;
        unsigned long long* dsc = desc + (size_t)g * MAXBLKS;
        unsigned int* tkt = ticket + g;

        cudaStreamWaitEvent(st, s_root, 0);
        cudaMemsetAsync(cnt, 0, (size_t)n * sizeof(int), st);
        cudaMemsetAsync(dsc, 0, (size_t)nb * sizeof(unsigned long long), st);
        cudaMemsetAsync(tkt, 0, sizeof(unsigned int), st);

        int eth = (nnz_[g] + 3) / 4;
        hist_kernel<<<(eth + 255) / 256, 256, 0, st>>>(rows_[g], nnz_[g], cnt);
        cudaEventRecord(s_hist[g], st);
        scan_kernel<<<nb, SCAN_B, 0, st>>>(cnt, n, G_.ebase, off, cur, dsc, tkt);
        bucket_kernel<<<(eth + 255) / 256, 256, 0, st>>>(rows_[g], cols_[g], vals_[g],
                                                         nnz_[g], G_.rbase, cur, edges);
        cudaEventRecord(s_done[g], st);
    }

    // main stream: f0 init, then degree-sort (needs only the hists)
    cudaMemsetAsync(dhist, 0, DBINS * sizeof(int), 0);
    init_kernel<<<(ntot * (D / 4) + 255) / 256, 256>>>(
        users_feature, items_feature, bundles_feature, U, NB, R1, R2, ntot, f0);
    for (int g = 0; g < 3; g++)
        cudaStreamWaitEvent(0, s_hist[g], 0);
    int rth = (ntot + 3) / 4;
    dhist_kernel<<<(rth + 255) / 256, 256>>>(counts, ntot, dhist);
    dscan_kernel<<<1, DBINS>>>(dhist);
    dscatter_kernel<<<(rth + 255) / 256, 256>>>(counts, ntot, dhist, perm);

    for (int g = 0; g < 3; g++)
        cudaStreamWaitEvent(0, s_done[g], 0);

    // merged spmm phases; 4 degree-matched rows per warp
    int blocks = (ntot + 31) / 32;
    spmm_kernel<true><<<blocks, 256>>>(edges, offs, perm, f0, f1,
                                       ntot, U, NI, NB, R1, R2, out);
    spmm_kernel<false><<<blocks, 256>>>(edges, offs, perm, f1, nullptr,
                                        ntot, U, NI, NB, R1, R2, out);
}

// round 12
// speedup vs baseline: 1.5990x; 1.5990x over previous
#include <cuda_runtime.h>
#include <cuda_fp16.h>
#include <cstdint>

#define D 64
#define MAXNTOT 340008
#define MAXNNZALL 4000008
#define SCAN_B 256
#define MAXBLKS ((150016 + SCAN_B - 1) / SCAN_B)

// ---- scratch (__device__ globals; no allocation allowed) ----
__device__ __align__(16) __half g_f0[(size_t)MAXNTOT * D];   // ~43.5 MB
__device__ __align__(16) __half g_f1[(size_t)MAXNTOT * D];   // ~43.5 MB
__device__ __align__(16) float2 g_edges[MAXNNZALL];          // {global col bits, val}
__device__ int g_counts[MAXNTOT];
__device__ int g_offs[MAXNTOT + 1];
__device__ int g_cursor[MAXNTOT];
__device__ unsigned long long g_desc[3][MAXBLKS];
__device__ unsigned int g_ticket[3];

// ---- init: f0(fp16) = concat of all three propagation inputs ----
__global__ void init_kernel(const float* __restrict__ Uf, const float* __restrict__ If,
                            const float* __restrict__ Bf,
                            int U, int NB, int R1, int R2, int ntot,
                            __half* __restrict__ f0) {
    int idx = blockIdx.x * blockDim.x + threadIdx.x;
    if (idx >= ntot * (D / 4)) return;
    int row = idx >> 4;
    int c = (idx & 15) * 4;
    const float* src;
    if (row < R1) {
        src = (row < U) ? (Uf + (size_t)row * D) : (If + (size_t)(row - U) * D);
    } else if (row < R2) {
        int l = row - R1;
        src = (l < NB) ? (Bf + (size_t)l * D) : (If + (size_t)(l - NB) * D);
    } else {
        int l = row - R2;
        src = (l < U) ? (Uf + (size_t)l * D) : (Bf + (size_t)(l - U) * D);
    }
    float4 v = *(const float4*)(src + c);
    __half2 h0 = __floats2half2_rn(v.x, v.y);
    __half2 h1 = __floats2half2_rn(v.z, v.w);
    uint2 packed;
    packed.x = *(const unsigned int*)&h0;
    packed.y = *(const unsigned int*)&h1;
    *(uint2*)(f0 + (size_t)row * D + c) = packed;
}

// ---- per-graph histogram (4 edges/thread) ----
__global__ void hist_kernel(const int* __restrict__ rows, int nnz, int* __restrict__ counts) {
    int base = (blockIdx.x * blockDim.x + threadIdx.x) * 4;
    if (base + 4 <= nnz) {
        int4 r = *(const int4*)(rows + base);
        atomicAdd(&counts[r.x], 1); atomicAdd(&counts[r.y], 1);
        atomicAdd(&counts[r.z], 1); atomicAdd(&counts[r.w], 1);
    } else {
        for (int k = base; k < nnz; k++) atomicAdd(&counts[rows[k]], 1);
    }
}

// ---- per-graph decoupled-lookback scan; writes GLOBAL offsets (base = edge base) ----
__global__ void scan_kernel(const int* __restrict__ counts, int n, int base,
                            int* __restrict__ offs, int* __restrict__ cursor,
                            unsigned long long* __restrict__ desc,
                            unsigned int* __restrict__ ticket) {
    __shared__ int s_warp[8];
    __shared__ int s_bid;
    __shared__ int s_excl;
    int lane = threadIdx.x & 31;
    int wid = threadIdx.x >> 5;
    if (threadIdx.x == 0) s_bid = (int)atomicAdd(ticket, 1u);
    __syncthreads();
    int bid = s_bid;
    int i = bid * SCAN_B + threadIdx.x;
    int v = (i < n) ? counts[i] : 0;
    int x = v;
    #pragma unroll
    for (int o = 1; o < 32; o <<= 1) {
        int t = __shfl_up_sync(0xffffffffu, x, o);
        if (lane >= o) x += t;
    }
    if (lane == 31) s_warp[wid] = x;
    __syncthreads();
    if (wid == 0 && lane < 8) {
        int w = s_warp[lane];
        #pragma unroll
        for (int o = 1; o < 8; o <<= 1) {
            int t = __shfl_up_sync(0xffu, w, o);
            if (lane >= o) w += t;
        }
        s_warp[lane] = w;
    }
    __syncthreads();
    int incl = x + (wid ? s_warp[wid - 1] : 0);
    int total = s_warp[7];
    if (threadIdx.x == 0) {
        if (bid == 0) {
            atomicExch(&desc[0], (2ULL << 62) | (unsigned long long)(unsigned)total);
            s_excl = 0;
        } else {
            atomicExch(&desc[bid], (1ULL << 62) | (unsigned long long)(unsigned)total);
            int excl = 0;
            int j = bid - 1;
            while (true) {
                unsigned long long d;
                do { d = atomicAdd(&desc[j], 0ULL); } while ((d >> 62) == 0ULL);
                excl += (int)(unsigned)d;
                if ((d >> 62) == 2ULL) break;
                j--;
            }
            s_excl = excl;
            atomicExch(&desc[bid], (2ULL << 62) | (unsigned long long)(unsigned)(excl + total));
        }
    }
    __syncthreads();
    int excl = s_excl;
    if (i < n) {
        int inc = incl + excl + base;
        offs[i + 1] = inc;
        cursor[i] = inc - v;
        if (i == 0) offs[0] = base;
    }
}

// ---- per-graph bucket: edges -> (GLOBAL col = local + cbase, val) ----
__global__ void bucket_kernel(const int* __restrict__ rows, const int* __restrict__ cols,
                              const float* __restrict__ vals, int nnz, int cbase,
                              int* __restrict__ cursor, float2* __restrict__ edges) {
    int base = (blockIdx.x * blockDim.x + threadIdx.x) * 4;
    if (base + 4 <= nnz) {
        int4 r = *(const int4*)(rows + base);
        int4 c = *(const int4*)(cols + base);
        float4 v = *(const float4*)(vals + base);
        int p0 = atomicAdd(&cursor[r.x], 1);
        int p1 = atomicAdd(&cursor[r.y], 1);
        int p2 = atomicAdd(&cursor[r.z], 1);
        int p3 = atomicAdd(&cursor[r.w], 1);
        edges[p0] = make_float2(__int_as_float(c.x + cbase), v.x);
        edges[p1] = make_float2(__int_as_float(c.y + cbase), v.y);
        edges[p2] = make_float2(__int_as_float(c.z + cbase), v.z);
        edges[p3] = make_float2(__int_as_float(c.w + cbase), v.w);
    } else {
        for (int k = base; k < nnz; k++) {
            int pos = atomicAdd(&cursor[rows[k]], 1);
            edges[pos] = make_float2(__int_as_float(cols[k] + cbase), vals[k]);
        }
    }
}

// map global row -> output row pointer (fixed packing of the 6 tables)
__device__ __forceinline__ float* out_ptr(float* out, int row, int U, int NI, int NB,
                                          int R1, int R2) {
    size_t off;
    if (row < R1) {
        off = (row < U) ? (size_t)row : (size_t)(2 * U + 2 * NB) + (row - U);
    } else if (row < R2) {
        int l = row - R1;
        off = (l < NB) ? (size_t)(2 * U) + l : (size_t)(2 * U + 2 * NB + NI) + (l - NB);
    } else {
        int l = row - R2;
        off = (l < U) ? (size_t)U + l : (size_t)(2 * U + NB) + (l - U);
    }
    return out + off * D;
}

#define EPAD make_float2(__int_as_float(0), 0.0f)

__device__ __forceinline__ void fma8(float* acc, float w, uint4 r) {
    float2 p0 = __half22float2(*(__half2*)&r.x);
    float2 p1 = __half22float2(*(__half2*)&r.y);
    float2 p2 = __half22float2(*(__half2*)&r.z);
    float2 p3 = __half22float2(*(__half2*)&r.w);
    acc[0] += w * p0.x; acc[1] += w * p0.y;
    acc[2] += w * p1.x; acc[3] += w * p1.y;
    acc[4] += w * p2.x; acc[5] += w * p2.y;
    acc[6] += w * p3.x; acc[7] += w * p3.y;
}

// ---- fused gather-SpMM over row window [rbase, rbase+n):
// one row per 8-lane quarter (4 independent rows/warp), natural row order.
template <bool FIRST>
__global__ void __launch_bounds__(256)
spmm_kernel(const float2* __restrict__ edges, const int* __restrict__ offs,
            const __half* __restrict__ fin, __half* __restrict__ fnext,
            int rbase, int n, int U, int NI, int NB, int R1, int R2,
            float* __restrict__ out) {
    int warp = blockIdx.x * (blockDim.x >> 5) + (threadIdx.x >> 5);
    int lane = threadIdx.x & 31;
    int quarter = lane >> 3;
    int sub = lane & 7;
    int idx = warp * 4 + quarter;
    if (idx >= n) return;
    int row = rbase + idx;
    unsigned qmask = 0xffu << (quarter * 8);

    int lo = __ldg(offs + row), hi = __ldg(offs + row + 1);

    float acc[8] = {0.f, 0.f, 0.f, 0.f, 0.f, 0.f, 0.f, 0.f};
    int i = lo;
    if (i < hi) {
        float2 c0 = __ldg(edges + i);
        float2 c1 = (i + 1 < hi) ? __ldg(edges + i + 1) : EPAD;
        float2 c2 = (i + 2 < hi) ? __ldg(edges + i + 2) : EPAD;
        float2 c3 = (i + 3 < hi) ? __ldg(edges + i + 3) : EPAD;
        while (true) {
            uint4 r0 = *((const uint4*)(fin + (size_t)__float_as_int(c0.x) * D) + sub);
            uint4 r1 = *((const uint4*)(fin + (size_t)__float_as_int(c1.x) * D) + sub);
            uint4 r2 = *((const uint4*)(fin + (size_t)__float_as_int(c2.x) * D) + sub);
            uint4 r3 = *((const uint4*)(fin + (size_t)__float_as_int(c3.x) * D) + sub);
            i += 4;
            bool more = (i < hi);
            float2 n0, n1, n2, n3;
            if (more) {
                n0 = __ldg(edges + i);
                n1 = (i + 1 < hi) ? __ldg(edges + i + 1) : EPAD;
                n2 = (i + 2 < hi) ? __ldg(edges + i + 2) : EPAD;
                n3 = (i + 3 < hi) ? __ldg(edges + i + 3) : EPAD;
            }
            fma8(acc, c0.y, r0);
            fma8(acc, c1.y, r1);
            fma8(acc, c2.y, r2);
            fma8(acc, c3.y, r3);
            if (!more) break;
            c0 = n0; c1 = n1; c2 = n2; c3 = n3;
        }
    }
    float ss = acc[0] * acc[0] + acc[1] * acc[1] + acc[2] * acc[2] + acc[3] * acc[3]
             + acc[4] * acc[4] + acc[5] * acc[5] + acc[6] * acc[6] + acc[7] * acc[7];
    #pragma unroll
    for (int o = 4; o; o >>= 1) ss += __shfl_xor_sync(qmask, ss, o);
    const float k = 1.0f / 3.0f;
    float scale = k / fmaxf(sqrtf(ss), 1e-12f);

    float* dst = out_ptr(out, row, U, NI, NB, R1, R2);
    if (FIRST) {
        __half2 h0 = __floats2half2_rn(acc[0], acc[1]);
        __half2 h1 = __floats2half2_rn(acc[2], acc[3]);
        __half2 h2 = __floats2half2_rn(acc[4], acc[5]);
        __half2 h3 = __floats2half2_rn(acc[6], acc[7]);
        uint4 packed;
        packed.x = *(const unsigned int*)&h0;
        packed.y = *(const unsigned int*)&h1;
        packed.z = *(const unsigned int*)&h2;
        packed.w = *(const unsigned int*)&h3;
        *((uint4*)(fnext + (size_t)row * D) + sub) = packed;
        uint4 r = *((const uint4*)(fin + (size_t)row * D) + sub);
        float2 p0 = __half22float2(*(__half2*)&r.x);
        float2 p1 = __half22float2(*(__half2*)&r.y);
        float2 p2 = __half22float2(*(__half2*)&r.z);
        float2 p3 = __half22float2(*(__half2*)&r.w);
        float4* d = (float4*)dst + sub * 2;
        d[0] = make_float4(p0.x * k + acc[0] * scale, p0.y * k + acc[1] * scale,
                           p1.x * k + acc[2] * scale, p1.y * k + acc[3] * scale);
        d[1] = make_float4(p2.x * k + acc[4] * scale, p2.y * k + acc[5] * scale,
                           p3.x * k + acc[6] * scale, p3.y * k + acc[7] * scale);
    } else {
        float4* d = (float4*)dst + sub * 2;
        float4 o0 = d[0], o1 = d[1];
        o0.x += acc[0] * scale; o0.y += acc[1] * scale;
        o0.z += acc[2] * scale; o0.w += acc[3] * scale;
        o1.x += acc[4] * scale; o1.y += acc[5] * scale;
        o1.z += acc[6] * scale; o1.w += acc[7] * scale;
        d[0] = o0; d[1] = o1;
    }
}

// ---- persistent streams/events ----
static cudaStream_t s_strm[3];
static cudaEvent_t s_root, s_init, s_done[3];
static bool s_ready = false;

extern "C" void kernel_launch(void* const* d_in, const int* in_sizes, int n_in,
                              void* d_out, int out_size) {
    const float* users_feature   = (const float*)d_in[0];
    const float* items_feature   = (const float*)d_in[1];
    const float* bundles_feature = (const float*)d_in[2];
    const float* vals_[3] = {(const float*)d_in[3], (const float*)d_in[4], (const float*)d_in[5]};
    const int* rows_[3] = {(const int*)d_in[6], (const int*)d_in[8], (const int*)d_in[10]};
    const int* cols_[3] = {(const int*)d_in[7], (const int*)d_in[9], (const int*)d_in[11]};

    int U  = in_sizes[0] / D;
    int NI = in_sizes[1] / D;
    int NB = in_sizes[2] / D;
    int nnz_[3] = {in_sizes[3], in_sizes[4], in_sizes[5]};   // UI, BI, UB

    int R1 = U + NI;
    int R2 = R1 + NB + NI;
    int ntot = R2 + U + NB;

    if (!s_ready) {
        for (int g = 0; g < 3; g++) {
            cudaStreamCreateWithFlags(&s_strm[g], cudaStreamNonBlocking);
            cudaEventCreateWithFlags(&s_done[g], cudaEventDisableTiming);
        }
        cudaEventCreateWithFlags(&s_root, cudaEventDisableTiming);
        cudaEventCreateWithFlags(&s_init, cudaEventDisableTiming);
        s_ready = true;
    }

    float* out = (float*)d_out;
    __half *f0, *f1;
    float2* edges;
    int *counts, *offs, *cursor;
    unsigned long long* desc;
    unsigned int* ticket;
    cudaGetSymbolAddress((void**)&f0, g_f0);
    cudaGetSymbolAddress((void**)&f1, g_f1);
    cudaGetSymbolAddress((void**)&edges, g_edges);
    cudaGetSymbolAddress((void**)&counts, g_counts);
    cudaGetSymbolAddress((void**)&offs, g_offs);
    cudaGetSymbolAddress((void**)&cursor, g_cursor);
    cudaGetSymbolAddress((void**)&desc, g_desc);
    cudaGetSymbolAddress((void**)&ticket, g_ticket);

    struct G { int rbase, n, ebase; };
    G gs[3] = {
        {0,  U + NI,  0},
        {R1, NB + NI, nnz_[0]},
        {R2, U + NB,  nnz_[0] + nnz_[1]},
    };

    // fork: per-graph CSR builds on 3 side streams; f0 init on main stream
    cudaEventRecord(s_root, 0);
    for (int g = 0; g < 3; g++) {
        cudaStream_t st = s_strm[g];
        const G& G_ = gs[g];
        int n = G_.n;
        int nb = (n + SCAN_B - 1) / SCAN_B;
        int* cnt = counts + G_.rbase;
        int* off = offs + G_.rbase;
        int* cur = cursor + G_.rbase;
        unsigned long long* dsc = desc + (size_t)g * MAXBLKS;
        unsigned int* tkt = ticket + g;

        cudaStreamWaitEvent(st, s_root, 0);
        cudaMemsetAsync(cnt, 0, (size_t)n * sizeof(int), st);
        cudaMemsetAsync(dsc, 0, (size_t)nb * sizeof(unsigned long long), st);
        cudaMemsetAsync(tkt, 0, sizeof(unsigned int), st);

        int eth = (nnz_[g] + 3) / 4;
        hist_kernel<<<(eth + 255) / 256, 256, 0, st>>>(rows_[g], nnz_[g], cnt);
        scan_kernel<<<nb, SCAN_B, 0, st>>>(cnt, n, G_.ebase, off, cur, dsc, tkt);
        bucket_kernel<<<(eth + 255) / 256, 256, 0, st>>>(rows_[g], cols_[g], vals_[g],
                                                         nnz_[g], G_.rbase, cur, edges);
        cudaEventRecord(s_done[g], st);
    }

    // main stream: f0 init
    init_kernel<<<(ntot * (D / 4) + 255) / 256, 256>>>(
        users_feature, items_feature, bundles_feature, U, NB, R1, R2, ntot, f0);
    cudaEventRecord(s_init, 0);

    // per-graph spmm1 on the build stream as soon as its CSR + init are done
    for (int g = 0; g < 3; g++) {
        cudaStream_t st = s_strm[g];
        const G& G_ = gs[g];
        cudaStreamWaitEvent(st, s_init, 0);
        int blocks = (G_.n + 31) / 32;
        spmm_kernel<true><<<blocks, 256, 0, st>>>(edges, offs, f0, f1,
                                                  G_.rbase, G_.n, U, NI, NB, R1, R2, out);
        cudaEventRecord(s_done[g], st);
    }

    for (int g = 0; g < 3; g++)
        cudaStreamWaitEvent(0, s_done[g], 0);

    // merged spmm2 over all rows on the main stream
    int blocks = (ntot + 31) / 32;
    spmm_kernel<false><<<blocks, 256>>>(edges, offs, f1, nullptr,
                                        0, ntot, U, NI, NB, R1, R2, out);
}